// round 9
// baseline (speedup 1.0000x reference)
#include <cuda_runtime.h>
#include <cstdint>

#define NB  4
#define NTQ 512
#define NTK 512
#define NE  128
#define NF  256   // TWO_E

// Scratch (no allocations allowed)
__device__ float g_qproj[NB * NTQ * NE];               // 1 MB
__device__ float g_kproj[NB * NTK * NE];               // 1 MB
__device__ float g_p[(size_t)NB * NTK * NTQ];          // 4 MB (unnormalized exp)
__device__ float g_zr[NB * NTK];                       // 1/rowsum per (b,t)

__device__ __forceinline__ float tanh_fast(float x) {
    float y;
    asm("tanh.approx.f32 %0, %1;" : "=f"(y) : "f"(x));
    return y;
}

// ---- packed fp32x2 helpers (FFMA2/FMUL2; bit-exact IEEE fp32 per lane) ----
__device__ __forceinline__ unsigned long long pack2(float x, float y) {
    unsigned long long r;
    asm("mov.b64 %0, {%1, %2};" : "=l"(r) : "f"(x), "f"(y));
    return r;
}
__device__ __forceinline__ void ffma2(unsigned long long& d,
                                      unsigned long long a, unsigned long long b) {
    asm("fma.rn.f32x2 %0, %1, %2, %0;" : "+l"(d) : "l"(a), "l"(b));
}
__device__ __forceinline__ unsigned long long mul2(unsigned long long a,
                                                   unsigned long long b) {
    unsigned long long r;
    asm("mul.rn.f32x2 %0, %1, %2;" : "=l"(r) : "l"(a), "l"(b));
    return r;
}
__device__ __forceinline__ float2 unpack2(unsigned long long v) {
    float2 f;
    asm("mov.b64 {%0, %1}, %2;" : "=f"(f.x), "=f"(f.y) : "l"(v));
    return f;
}

// ---- cp.async helpers ----
__device__ __forceinline__ uint32_t smem_u32(const void* p) {
    return (uint32_t)__cvta_generic_to_shared(p);
}
__device__ __forceinline__ void cp16(uint32_t dst, const void* src) {
    asm volatile("cp.async.ca.shared.global [%0], [%1], 16;"
                 :: "r"(dst), "l"(src) : "memory");
}
__device__ __forceinline__ void cp_commit() {
    asm volatile("cp.async.commit_group;" ::: "memory");
}
template <int N>
__device__ __forceinline__ void cp_wait() {
    asm volatile("cp.async.wait_group %0;" :: "n"(N) : "memory");
}

// ---------------------------------------------------------------------------
// Kernel A: projections.  C[r,e] = sum_f A[r,f] * W[f,e]
// A: [2048 x 256], W: [256 x 128].  blockIdx.y selects (query,W1) / (key,W2).
// Tile 16x128, stage K=32, 256 THREADS, 2x4 micro-tile, f32x2 math.
// 2-buffer cp.async pipeline, ONE __syncthreads per iter (wait -> sync ->
// issue next into buf^1 -> compute buf).  8 warps/block -> 3.46 warps/SMSP.
// ---------------------------------------------------------------------------
__global__ __launch_bounds__(256) void proj_kernel(
    const float* __restrict__ query, const float* __restrict__ key,
    const float* __restrict__ W1, const float* __restrict__ W2)
{
    const float* A; const float* W; float* C;
    if (blockIdx.y == 0) { A = query; W = W1; C = g_qproj; }
    else                 { A = key;   W = W2; C = g_kproj; }

    __shared__ float As[2][16][32];    // [buf][m][k]  2KB/buf
    __shared__ float Bs[2][32][128];   // [buf][k][n] 16KB/buf

    const int tid = threadIdx.x;
    const int tx = tid & 31;           // 32 threads over N (x4 cols)
    const int ty = tid >> 5;           // 8 threads over M  (x2 rows)
    const int row0 = blockIdx.x * 16;

    // cp.async chunk mapping (16B chunks)
    const int a_r  = tid >> 3;             // A: 1 chunk for tid<128
    const int a_c  = (tid & 7) << 2;
    const float* a_src = A + (size_t)(row0 + a_r) * NF + a_c;

    auto issue_stage = [&](int st) {       // stage 0..7, buf = st&1
        const int buf = st & 1;
        const int kk  = st << 5;
        if (tid < 128)
            cp16(smem_u32(&As[buf][a_r][a_c]), a_src + kk);
        #pragma unroll
        for (int i = 0; i < 4; i++) {      // B: 4 chunks/thread
            int c  = tid + (i << 8);
            int k  = c >> 5;
            int n4 = (c & 31) << 2;
            cp16(smem_u32(&Bs[buf][k][n4]), W + (size_t)(kk + k) * NE + n4);
        }
        cp_commit();
    };

    issue_stage(0);

    unsigned long long acc2[2][2];
    #pragma unroll
    for (int i = 0; i < 2; i++) { acc2[i][0] = 0ULL; acc2[i][1] = 0ULL; }

    #pragma unroll
    for (int it = 0; it < 8; it++) {
        const int buf = it & 1;
        cp_wait<0>();                  // stage it landed
        __syncthreads();               // publishes it; retires readers of buf^1
        if (it < 7) issue_stage(it + 1);

        #pragma unroll
        for (int k4 = 0; k4 < 32; k4 += 4) {
            float a[2][4];
            #pragma unroll
            for (int i = 0; i < 2; i++) {
                float4 av = *(const float4*)&As[buf][(ty << 1) + i][k4];  // bcast
                a[i][0] = av.x; a[i][1] = av.y; a[i][2] = av.z; a[i][3] = av.w;
            }
            #pragma unroll
            for (int j = 0; j < 4; j++) {
                ulonglong2 bp = *(const ulonglong2*)&Bs[buf][k4 + j][tx << 2];
                #pragma unroll
                for (int i = 0; i < 2; i++) {
                    unsigned long long aa = pack2(a[i][j], a[i][j]);
                    ffma2(acc2[i][0], aa, bp.x);
                    ffma2(acc2[i][1], aa, bp.y);
                }
            }
        }
    }

    #pragma unroll
    for (int i = 0; i < 2; i++) {
        float2 f01 = unpack2(acc2[i][0]);
        float2 f23 = unpack2(acc2[i][1]);
        float4 v = make_float4(f01.x, f01.y, f23.x, f23.y);
        *(float4*)(C + (size_t)(row0 + (ty << 1) + i) * NE + (tx << 2)) = v;
    }
}

// ---------------------------------------------------------------------------
// Kernel B: scores + exp + row-reciprocal.  MUFU(tanh)-bound (at floor).
// R5 form: padded smem, register prefetch, CONSTANT-index compute loop.
// p[b,t,q] = exp(sum_e vc[e]*tanh(k[t,e]+q[q,e]))  (no max pass; |sjt| <= ~9)
// ---------------------------------------------------------------------------
__global__ __launch_bounds__(256) void score_kernel(const float* __restrict__ vc)
{
    __shared__ float ks[8][128];
    __shared__ float qs[2][32][129];   // +1 pad: lane-per-row reads conflict-free
    __shared__ float vcs[128];

    const int b   = blockIdx.y;
    const int t0  = blockIdx.x << 3;
    const int tid = threadIdx.x;
    const int w    = tid >> 5;
    const int lane = tid & 31;

    {   // k tile [8 x 128]
        int lin = tid << 2;
        int r = lin >> 7, c = lin & 127;
        *(float4*)&ks[r][c] =
            *(const float4*)(g_kproj + (size_t)(b * NTK + t0 + r) * NE + c);
    }
    if (tid < 128) vcs[tid] = vc[tid];

    // q chunk load mapping: thread covers column c0, rows rbase, rbase+2, ...
    const int c0    = tid & 127;
    const int rbase = tid >> 7;        // 0 or 1
    const float* qbase = g_qproj + (size_t)b * NTQ * NE + rbase * NE + c0;

    float pref[16];
    #pragma unroll
    for (int i = 0; i < 16; i++)       // chunk 0
        pref[i] = qbase[(size_t)(2 * i) * NE];
    #pragma unroll
    for (int i = 0; i < 16; i++)
        qs[0][rbase + 2 * i][c0] = pref[i];
    __syncthreads();

    const int t = t0 + w;
    float* __restrict__ prow = g_p + ((size_t)b * NTK + t) * NTQ;
    float zsum = 0.f;

    for (int ch = 0; ch < 16; ch++) {
        const int buf = ch & 1;
        if (ch < 15) {                 // prefetch next 32-q chunk (overlaps tanh loop)
            const float* src = qbase + (size_t)(ch + 1) * 32 * NE;
            #pragma unroll
            for (int i = 0; i < 16; i++)
                pref[i] = src[(size_t)(2 * i) * NE];
        }

        const float* __restrict__ kr = ks[w];          // warp broadcast
        const float* __restrict__ q0 = qs[buf][lane];
        float acc0 = 0.f;
        #pragma unroll 16
        for (int e = 0; e < 128; e++)
            acc0 += vcs[e] * tanh_fast(kr[e] + q0[e]);

        float p0 = __expf(acc0);
        prow[ch * 32 + lane] = p0;
        zsum += p0;

        if (ch < 15) {
            __syncthreads();           // all warps done with buf^1 (chunk ch-1)
            #pragma unroll
            for (int i = 0; i < 16; i++)
                qs[buf ^ 1][rbase + 2 * i][c0] = pref[i];
            __syncthreads();
        }
    }

    #pragma unroll
    for (int off = 16; off; off >>= 1)
        zsum += __shfl_xor_sync(0xffffffffu, zsum, off);
    if (lane == 0) g_zr[b * NTK + t] = 1.0f / zsum;
}

// ---------------------------------------------------------------------------
// Kernel C: out[b,d,q] = sum_t (value[b,d,t] * zr[b,t]) * p[b,t,q]
// SGEMM M=256, N=512, K=512 per batch; tile 32x64, 256 THREADS, 2x4 micro,
// f32x2 math.  3-stage cp.async pipeline, ONE sync per iter.
// smem = 3*(4KB+8KB) + 2KB = 38KB.  zr folded into B rows in-loop via mul2.
// 8 warps/block -> 3.46 warps/SMSP.
// ---------------------------------------------------------------------------
__global__ __launch_bounds__(256) void out_kernel(
    const float* __restrict__ value, float* __restrict__ out)
{
    __shared__ float As[3][32][32];    // [buf][m][k]  4KB/buf
    __shared__ float Bs[3][32][64];    // [buf][k][n]  8KB/buf
    __shared__ float zrs[NTK];

    const int b   = blockIdx.z;
    const int n0  = blockIdx.x << 6;
    const int m0  = blockIdx.y << 5;
    const int tid = threadIdx.x;
    const int tx  = tid & 15;          // 16 over N (x4 cols)
    const int ty  = tid >> 4;          // 16 over M (x2 rows)

    #pragma unroll
    for (int i = 0; i < 2; i++)
        zrs[tid + (i << 8)] = g_zr[b * NTK + tid + (i << 8)];

    const float* Av = value + (size_t)b * NF * NTK;
    const float* Bp = g_p   + (size_t)b * NTK * NTQ;

    auto issue_stage = [&](int st) {       // stage 0..15, buf = st%3
        const int buf = st % 3;
        const int kk  = st << 5;
        {                                  // A: 1 chunk/thread
            int m  = tid >> 3;
            int kc = (tid & 7) << 2;
            cp16(smem_u32(&As[buf][m][kc]),
                 Av + (size_t)(m0 + m) * NTK + kk + kc);
        }
        #pragma unroll
        for (int i = 0; i < 2; i++) {      // B: 2 chunks/thread
            int c  = tid + (i << 8);
            int k  = c >> 4;
            int n4 = (c & 15) << 2;
            cp16(smem_u32(&Bs[buf][k][n4]),
                 Bp + (size_t)(kk + k) * NTQ + n0 + n4);
        }
        cp_commit();
    };

    issue_stage(0);
    issue_stage(1);

    unsigned long long acc2[2][2];
    #pragma unroll
    for (int i = 0; i < 2; i++) { acc2[i][0] = 0ULL; acc2[i][1] = 0ULL; }

    #pragma unroll
    for (int it = 0; it < 16; it++) {
        const int buf = it % 3;
        const int kk  = it << 5;
        if (it < 15) cp_wait<1>(); else cp_wait<0>();
        __syncthreads();               // publishes stage it; also zrs on it=0
        if (it < 14) issue_stage(it + 2);

        #pragma unroll
        for (int k4 = 0; k4 < 32; k4 += 4) {
            float a[2][4];
            #pragma unroll
            for (int i = 0; i < 2; i++) {
                float4 av = *(const float4*)&As[buf][(ty << 1) + i][k4];  // bcast
                a[i][0] = av.x; a[i][1] = av.y; a[i][2] = av.z; a[i][3] = av.w;
            }
            float4 z4 = *(const float4*)&zrs[kk + k4];                    // bcast
            float zk[4] = {z4.x, z4.y, z4.z, z4.w};
            #pragma unroll
            for (int j = 0; j < 4; j++) {
                ulonglong2 bp = *(const ulonglong2*)&Bs[buf][k4 + j][tx << 2];
                unsigned long long zz = pack2(zk[j], zk[j]);
                unsigned long long b0 = mul2(bp.x, zz);   // fold 1/Z into B row
                unsigned long long b1 = mul2(bp.y, zz);
                #pragma unroll
                for (int i = 0; i < 2; i++) {
                    unsigned long long aa = pack2(a[i][j], a[i][j]);
                    ffma2(acc2[i][0], aa, b0);
                    ffma2(acc2[i][1], aa, b1);
                }
            }
        }
    }

    #pragma unroll
    for (int i = 0; i < 2; i++) {
        float2 f01 = unpack2(acc2[i][0]);
        float2 f23 = unpack2(acc2[i][1]);
        float4 v = make_float4(f01.x, f01.y, f23.x, f23.y);
        *(float4*)(out + (size_t)(b * NF + m0 + (ty << 1) + i) * NTQ + n0 + (tx << 2)) = v;
    }
}

// ---------------------------------------------------------------------------
extern "C" void kernel_launch(void* const* d_in, const int* in_sizes, int n_in,
                              void* d_out, int out_size)
{
    const float* query = (const float*)d_in[0];
    const float* key   = (const float*)d_in[1];
    const float* value = (const float*)d_in[2];
    const float* W1    = (const float*)d_in[3];
    const float* W2    = (const float*)d_in[4];
    const float* vc    = (const float*)d_in[5];
    float* out = (float*)d_out;

    proj_kernel <<<dim3(128, 2), 256>>>(query, key, W1, W2);  // 2048/16 rows x {q,k}
    score_kernel<<<dim3(64, 4), 256>>>(vc);                   // TK/8 x B
    out_kernel  <<<dim3(8, 8, 4), 256>>>(value, out);         // N/64 x M/32 x B
}

// round 10
// speedup vs baseline: 1.1469x; 1.1469x over previous
#include <cuda_runtime.h>
#include <cstdint>

#define NB  4
#define NTQ 512
#define NTK 512
#define NE  128
#define NF  256   // TWO_E

// Scratch (no allocations allowed)
__device__ float g_qproj[NB * NTQ * NE];               // 1 MB
__device__ float g_kproj[NB * NTK * NE];               // 1 MB
__device__ float g_p[(size_t)NB * NTK * NTQ];          // 4 MB (unnormalized exp)
__device__ float g_zr[NB * NTK];                       // 1/rowsum per (b,t)

__device__ __forceinline__ float tanh_fast(float x) {
    float y;
    asm("tanh.approx.f32 %0, %1;" : "=f"(y) : "f"(x));
    return y;
}

// ---- packed fp32x2 helpers (FFMA2/FMUL2; bit-exact IEEE fp32 per lane) ----
__device__ __forceinline__ unsigned long long pack2(float x, float y) {
    unsigned long long r;
    asm("mov.b64 %0, {%1, %2};" : "=l"(r) : "f"(x), "f"(y));
    return r;
}
__device__ __forceinline__ void ffma2(unsigned long long& d,
                                      unsigned long long a, unsigned long long b) {
    asm("fma.rn.f32x2 %0, %1, %2, %0;" : "+l"(d) : "l"(a), "l"(b));
}
__device__ __forceinline__ unsigned long long mul2(unsigned long long a,
                                                   unsigned long long b) {
    unsigned long long r;
    asm("mul.rn.f32x2 %0, %1, %2;" : "=l"(r) : "l"(a), "l"(b));
    return r;
}
__device__ __forceinline__ float2 unpack2(unsigned long long v) {
    float2 f;
    asm("mov.b64 {%0, %1}, %2;" : "=f"(f.x), "=f"(f.y) : "l"(v));
    return f;
}

// ---- cp.async helpers ----
__device__ __forceinline__ uint32_t smem_u32(const void* p) {
    return (uint32_t)__cvta_generic_to_shared(p);
}
__device__ __forceinline__ void cp16(uint32_t dst, const void* src) {
    asm volatile("cp.async.ca.shared.global [%0], [%1], 16;"
                 :: "r"(dst), "l"(src) : "memory");
}
__device__ __forceinline__ void cp_commit() {
    asm volatile("cp.async.commit_group;" ::: "memory");
}
template <int N>
__device__ __forceinline__ void cp_wait() {
    asm volatile("cp.async.wait_group %0;" :: "n"(N) : "memory");
}

// ---------------------------------------------------------------------------
// Kernel A: projections.  C[r,e] = sum_f A[r,f] * W[f,e]
// A: [2048 x 256], W: [256 x 128].  blockIdx.y selects (query,W1) / (key,W2).
// Tile 32x128, stage K=32, 256 threads, 4x4 micro-tile, f32x2 math.
// grid = 64 x 2 = 128 blocks -> SINGLE WAVE on 148 SMs (was 1.73 waves).
// 2-buffer cp.async, ONE __syncthreads per iter (wait -> sync -> issue next
// into buf^1 -> compute buf; buf^1's readers all passed this barrier).
// smem = 2*(4KB + 16KB) = 40KB.
// ---------------------------------------------------------------------------
__global__ __launch_bounds__(256) void proj_kernel(
    const float* __restrict__ query, const float* __restrict__ key,
    const float* __restrict__ W1, const float* __restrict__ W2)
{
    const float* A; const float* W; float* C;
    if (blockIdx.y == 0) { A = query; W = W1; C = g_qproj; }
    else                 { A = key;   W = W2; C = g_kproj; }

    __shared__ float As[2][32][32];    // [buf][m][k]  4KB/buf
    __shared__ float Bs[2][32][128];   // [buf][k][n] 16KB/buf

    const int tid = threadIdx.x;
    const int tx = tid & 31;           // 32 threads over N (x4 cols)
    const int ty = tid >> 5;           // 8 threads over M  (x4 rows)
    const int row0 = blockIdx.x * 32;

    // cp.async chunk mapping (16B chunks)
    const int a_r  = tid >> 3;             // A: 1 chunk/thread (32 rows x 32 k)
    const int a_c  = (tid & 7) << 2;
    const float* a_src = A + (size_t)(row0 + a_r) * NF + a_c;

    auto issue_stage = [&](int st) {       // stage 0..7, buf = st&1
        const int buf = st & 1;
        const int kk  = st << 5;
        cp16(smem_u32(&As[buf][a_r][a_c]), a_src + kk);
        #pragma unroll
        for (int i = 0; i < 4; i++) {      // B: 4 chunks/thread (32 k x 128 n)
            int c  = tid + (i << 8);
            int k  = c >> 5;
            int n4 = (c & 31) << 2;
            cp16(smem_u32(&Bs[buf][k][n4]), W + (size_t)(kk + k) * NE + n4);
        }
        cp_commit();
    };

    issue_stage(0);

    unsigned long long acc2[4][2];
    #pragma unroll
    for (int i = 0; i < 4; i++) { acc2[i][0] = 0ULL; acc2[i][1] = 0ULL; }

    #pragma unroll
    for (int it = 0; it < 8; it++) {
        const int buf = it & 1;
        cp_wait<0>();                  // stage it landed
        __syncthreads();               // publishes it; retires readers of buf^1
        if (it < 7) issue_stage(it + 1);

        #pragma unroll
        for (int k4 = 0; k4 < 32; k4 += 4) {
            float a[4][4];
            #pragma unroll
            for (int i = 0; i < 4; i++) {
                float4 av = *(const float4*)&As[buf][(ty << 2) + i][k4];  // bcast
                a[i][0] = av.x; a[i][1] = av.y; a[i][2] = av.z; a[i][3] = av.w;
            }
            #pragma unroll
            for (int j = 0; j < 4; j++) {
                ulonglong2 bp = *(const ulonglong2*)&Bs[buf][k4 + j][tx << 2];
                #pragma unroll
                for (int i = 0; i < 4; i++) {
                    unsigned long long aa = pack2(a[i][j], a[i][j]);
                    ffma2(acc2[i][0], aa, bp.x);
                    ffma2(acc2[i][1], aa, bp.y);
                }
            }
        }
    }

    #pragma unroll
    for (int i = 0; i < 4; i++) {
        float2 f01 = unpack2(acc2[i][0]);
        float2 f23 = unpack2(acc2[i][1]);
        float4 v = make_float4(f01.x, f01.y, f23.x, f23.y);
        *(float4*)(C + (size_t)(row0 + (ty << 2) + i) * NE + (tx << 2)) = v;
    }
}

// ---------------------------------------------------------------------------
// Kernel B: scores + exp + row-reciprocal.  MUFU(tanh)-bound (at floor).
// R5 form (part of every best run): padded smem, register prefetch,
// constant-index compute loop.
// p[b,t,q] = exp(sum_e vc[e]*tanh(k[t,e]+q[q,e]))  (no max pass; |sjt| <= ~9)
// ---------------------------------------------------------------------------
__global__ __launch_bounds__(256) void score_kernel(const float* __restrict__ vc)
{
    __shared__ float ks[8][128];
    __shared__ float qs[2][32][129];   // +1 pad: lane-per-row reads conflict-free
    __shared__ float vcs[128];

    const int b   = blockIdx.y;
    const int t0  = blockIdx.x << 3;
    const int tid = threadIdx.x;
    const int w    = tid >> 5;
    const int lane = tid & 31;

    {   // k tile [8 x 128]
        int lin = tid << 2;
        int r = lin >> 7, c = lin & 127;
        *(float4*)&ks[r][c] =
            *(const float4*)(g_kproj + (size_t)(b * NTK + t0 + r) * NE + c);
    }
    if (tid < 128) vcs[tid] = vc[tid];

    // q chunk load mapping: thread covers column c0, rows rbase, rbase+2, ...
    const int c0    = tid & 127;
    const int rbase = tid >> 7;        // 0 or 1
    const float* qbase = g_qproj + (size_t)b * NTQ * NE + rbase * NE + c0;

    float pref[16];
    #pragma unroll
    for (int i = 0; i < 16; i++)       // chunk 0
        pref[i] = qbase[(size_t)(2 * i) * NE];
    #pragma unroll
    for (int i = 0; i < 16; i++)
        qs[0][rbase + 2 * i][c0] = pref[i];
    __syncthreads();

    const int t = t0 + w;
    float* __restrict__ prow = g_p + ((size_t)b * NTK + t) * NTQ;
    float zsum = 0.f;

    for (int ch = 0; ch < 16; ch++) {
        const int buf = ch & 1;
        if (ch < 15) {                 // prefetch next 32-q chunk (overlaps tanh loop)
            const float* src = qbase + (size_t)(ch + 1) * 32 * NE;
            #pragma unroll
            for (int i = 0; i < 16; i++)
                pref[i] = src[(size_t)(2 * i) * NE];
        }

        const float* __restrict__ kr = ks[w];          // warp broadcast
        const float* __restrict__ q0 = qs[buf][lane];
        float acc0 = 0.f;
        #pragma unroll 16
        for (int e = 0; e < 128; e++)
            acc0 += vcs[e] * tanh_fast(kr[e] + q0[e]);

        float p0 = __expf(acc0);
        prow[ch * 32 + lane] = p0;
        zsum += p0;

        if (ch < 15) {
            __syncthreads();           // all warps done with buf^1 (chunk ch-1)
            #pragma unroll
            for (int i = 0; i < 16; i++)
                qs[buf ^ 1][rbase + 2 * i][c0] = pref[i];
            __syncthreads();
        }
    }

    #pragma unroll
    for (int off = 16; off; off >>= 1)
        zsum += __shfl_xor_sync(0xffffffffu, zsum, off);
    if (lane == 0) g_zr[b * NTK + t] = 1.0f / zsum;
}

// ---------------------------------------------------------------------------
// Kernel C: out[b,d,q] = sum_t (value[b,d,t] * zr[b,t]) * p[b,t,q]
// SGEMM M=256, N=512, K=512 per batch; tile 64x64, 256 threads, 4x4 micro,
// f32x2 math.  grid = 8 x 4 x 4 = 128 blocks -> SINGLE WAVE (was 1.73).
// 2-buffer cp.async, ONE sync per iter.  smem = 2*(8KB+8KB) + 2KB = 34KB.
// zr folded into B rows in-loop via mul2.
// ---------------------------------------------------------------------------
__global__ __launch_bounds__(256) void out_kernel(
    const float* __restrict__ value, float* __restrict__ out)
{
    __shared__ float As[2][64][32];    // [buf][m][k]  8KB/buf
    __shared__ float Bs[2][32][64];    // [buf][k][n]  8KB/buf
    __shared__ float zrs[NTK];

    const int b   = blockIdx.z;
    const int n0  = blockIdx.x << 6;
    const int m0  = blockIdx.y << 6;
    const int tid = threadIdx.x;
    const int tx  = tid & 15;          // 16 over N (x4 cols)
    const int ty  = tid >> 4;          // 16 over M (x4 rows)

    #pragma unroll
    for (int i = 0; i < 2; i++)
        zrs[tid + (i << 8)] = g_zr[b * NTK + tid + (i << 8)];

    const float* Av = value + (size_t)b * NF * NTK;
    const float* Bp = g_p   + (size_t)b * NTK * NTQ;

    auto issue_stage = [&](int st) {       // stage 0..15, buf = st&1
        const int buf = st & 1;
        const int kk  = st << 5;
        #pragma unroll
        for (int i = 0; i < 2; i++) {      // A: 2 chunks/thread (64 m x 32 k)
            int c  = tid + (i << 8);
            int m  = c >> 3;
            int kc = (c & 7) << 2;
            cp16(smem_u32(&As[buf][m][kc]),
                 Av + (size_t)(m0 + m) * NTK + kk + kc);
        }
        #pragma unroll
        for (int i = 0; i < 2; i++) {      // B: 2 chunks/thread (32 k x 64 n)
            int c  = tid + (i << 8);
            int k  = c >> 4;
            int n4 = (c & 15) << 2;
            cp16(smem_u32(&Bs[buf][k][n4]),
                 Bp + (size_t)(kk + k) * NTQ + n0 + n4);
        }
        cp_commit();
    };

    issue_stage(0);

    unsigned long long acc2[4][2];
    #pragma unroll
    for (int i = 0; i < 4; i++) { acc2[i][0] = 0ULL; acc2[i][1] = 0ULL; }

    #pragma unroll
    for (int it = 0; it < 16; it++) {
        const int buf = it & 1;
        const int kk  = it << 5;
        cp_wait<0>();                  // stage it landed
        __syncthreads();               // publishes it (+ zrs on it=0)
        if (it < 15) issue_stage(it + 1);

        #pragma unroll
        for (int k4 = 0; k4 < 32; k4 += 4) {
            float a[4][4];
            #pragma unroll
            for (int i = 0; i < 4; i++) {
                float4 av = *(const float4*)&As[buf][(ty << 2) + i][k4];
                a[i][0] = av.x; a[i][1] = av.y; a[i][2] = av.z; a[i][3] = av.w;
            }
            float4 z4 = *(const float4*)&zrs[kk + k4];                    // bcast
            float zk[4] = {z4.x, z4.y, z4.z, z4.w};
            #pragma unroll
            for (int j = 0; j < 4; j++) {
                ulonglong2 bp = *(const ulonglong2*)&Bs[buf][k4 + j][tx << 2];
                unsigned long long zz = pack2(zk[j], zk[j]);
                unsigned long long b0 = mul2(bp.x, zz);   // fold 1/Z into B row
                unsigned long long b1 = mul2(bp.y, zz);
                #pragma unroll
                for (int i = 0; i < 4; i++) {
                    unsigned long long aa = pack2(a[i][j], a[i][j]);
                    ffma2(acc2[i][0], aa, b0);
                    ffma2(acc2[i][1], aa, b1);
                }
            }
        }
    }

    #pragma unroll
    for (int i = 0; i < 4; i++) {
        float2 f01 = unpack2(acc2[i][0]);
        float2 f23 = unpack2(acc2[i][1]);
        float4 v = make_float4(f01.x, f01.y, f23.x, f23.y);
        *(float4*)(out + (size_t)(b * NF + m0 + (ty << 2) + i) * NTQ + n0 + (tx << 2)) = v;
    }
}

// ---------------------------------------------------------------------------
extern "C" void kernel_launch(void* const* d_in, const int* in_sizes, int n_in,
                              void* d_out, int out_size)
{
    const float* query = (const float*)d_in[0];
    const float* key   = (const float*)d_in[1];
    const float* value = (const float*)d_in[2];
    const float* W1    = (const float*)d_in[3];
    const float* W2    = (const float*)d_in[4];
    const float* vc    = (const float*)d_in[5];
    float* out = (float*)d_out;

    proj_kernel <<<dim3(64, 2), 256>>>(query, key, W1, W2);   // 2048/32 rows x {q,k}
    score_kernel<<<dim3(64, 4), 256>>>(vc);                   // TK/8 x B
    out_kernel  <<<dim3(8, 4, 4), 256>>>(value, out);         // N/64 x M/64 x B
}

// round 11
// speedup vs baseline: 1.2923x; 1.1267x over previous
#include <cuda_runtime.h>
#include <cuda_bf16.h>
#include <cstdint>

#define NB  4
#define NTQ 512
#define NTK 512
#define NE  128
#define NF  256   // TWO_E
#define NT2 256   // NTK/2 (t-pairs)

// Scratch (no allocations allowed)
__device__ float    g_qproj[NB * NTQ * NE];                 // 1 MB
__device__ float    g_kproj[NB * NTK * NE];                 // 1 MB
__device__ float    g_zr[NB * NTK];                         // 1/rowsum per (b,t)
__device__ uint32_t g_ph[(size_t)NB * NT2 * NTQ];           // 2 MB  p hi, bf16 t-pairs
__device__ uint32_t g_pl[(size_t)NB * NT2 * NTQ];           // 2 MB  p lo
__device__ uint32_t g_vh[(size_t)NB * NF * NT2];            // 1 MB  value*zr hi, bf16 t-pairs
__device__ uint32_t g_vl[(size_t)NB * NF * NT2];            // 1 MB  value*zr lo

__device__ __forceinline__ float tanh_fast(float x) {
    float y;
    asm("tanh.approx.f32 %0, %1;" : "=f"(y) : "f"(x));
    return y;
}

// ---- packed fp32x2 helpers ----
__device__ __forceinline__ unsigned long long pack2(float x, float y) {
    unsigned long long r;
    asm("mov.b64 %0, {%1, %2};" : "=l"(r) : "f"(x), "f"(y));
    return r;
}
__device__ __forceinline__ void ffma2(unsigned long long& d,
                                      unsigned long long a, unsigned long long b) {
    asm("fma.rn.f32x2 %0, %1, %2, %0;" : "+l"(d) : "l"(a), "l"(b));
}
__device__ __forceinline__ float2 unpack2(unsigned long long v) {
    float2 f;
    asm("mov.b64 {%0, %1}, %2;" : "=f"(f.x), "=f"(f.y) : "l"(v));
    return f;
}

// ---- cp.async helpers ----
__device__ __forceinline__ uint32_t smem_u32(const void* p) {
    return (uint32_t)__cvta_generic_to_shared(p);
}
__device__ __forceinline__ void cp16(uint32_t dst, const void* src) {
    asm volatile("cp.async.ca.shared.global [%0], [%1], 16;"
                 :: "r"(dst), "l"(src) : "memory");
}
__device__ __forceinline__ void cp_commit() {
    asm volatile("cp.async.commit_group;" ::: "memory");
}
template <int N>
__device__ __forceinline__ void cp_wait() {
    asm volatile("cp.async.wait_group %0;" :: "n"(N) : "memory");
}

// ---- bf16 split helpers ----
__device__ __forceinline__ void bf16_split(float x, uint16_t& hi, uint16_t& lo) {
    __nv_bfloat16 h = __float2bfloat16(x);
    float r = x - __bfloat162float(h);
    __nv_bfloat16 l = __float2bfloat16(r);
    hi = __bfloat16_as_ushort(h);
    lo = __bfloat16_as_ushort(l);
}

// ---- mma.sync m16n8k16 bf16 (fp32 accum) ----
__device__ __forceinline__ void mma_bf16(float* c, const uint32_t* a,
                                         uint32_t b0, uint32_t b1) {
    asm volatile(
        "mma.sync.aligned.m16n8k16.row.col.f32.bf16.bf16.f32 "
        "{%0,%1,%2,%3}, {%4,%5,%6,%7}, {%8,%9}, {%0,%1,%2,%3};"
        : "+f"(c[0]), "+f"(c[1]), "+f"(c[2]), "+f"(c[3])
        : "r"(a[0]), "r"(a[1]), "r"(a[2]), "r"(a[3]), "r"(b0), "r"(b1));
}

// ---------------------------------------------------------------------------
// Kernel A: projections (unchanged from R10 best: 12.8us).
// Tile 32x128, stage K=32, 256 threads, 4x4 micro-tile, f32x2, 2-buffer
// cp.async, one sync/iter.  grid 64x2 = 128 blocks = single wave.
// ---------------------------------------------------------------------------
__global__ __launch_bounds__(256) void proj_kernel(
    const float* __restrict__ query, const float* __restrict__ key,
    const float* __restrict__ W1, const float* __restrict__ W2)
{
    const float* A; const float* W; float* C;
    if (blockIdx.y == 0) { A = query; W = W1; C = g_qproj; }
    else                 { A = key;   W = W2; C = g_kproj; }

    __shared__ float As[2][32][32];
    __shared__ float Bs[2][32][128];

    const int tid = threadIdx.x;
    const int tx = tid & 31;
    const int ty = tid >> 5;
    const int row0 = blockIdx.x * 32;

    const int a_r  = tid >> 3;
    const int a_c  = (tid & 7) << 2;
    const float* a_src = A + (size_t)(row0 + a_r) * NF + a_c;

    auto issue_stage = [&](int st) {
        const int buf = st & 1;
        const int kk  = st << 5;
        cp16(smem_u32(&As[buf][a_r][a_c]), a_src + kk);
        #pragma unroll
        for (int i = 0; i < 4; i++) {
            int c  = tid + (i << 8);
            int k  = c >> 5;
            int n4 = (c & 31) << 2;
            cp16(smem_u32(&Bs[buf][k][n4]), W + (size_t)(kk + k) * NE + n4);
        }
        cp_commit();
    };

    issue_stage(0);

    unsigned long long acc2[4][2];
    #pragma unroll
    for (int i = 0; i < 4; i++) { acc2[i][0] = 0ULL; acc2[i][1] = 0ULL; }

    #pragma unroll
    for (int it = 0; it < 8; it++) {
        const int buf = it & 1;
        cp_wait<0>();
        __syncthreads();
        if (it < 7) issue_stage(it + 1);

        #pragma unroll
        for (int k4 = 0; k4 < 32; k4 += 4) {
            float a[4][4];
            #pragma unroll
            for (int i = 0; i < 4; i++) {
                float4 av = *(const float4*)&As[buf][(ty << 2) + i][k4];
                a[i][0] = av.x; a[i][1] = av.y; a[i][2] = av.z; a[i][3] = av.w;
            }
            #pragma unroll
            for (int j = 0; j < 4; j++) {
                ulonglong2 bp = *(const ulonglong2*)&Bs[buf][k4 + j][tx << 2];
                #pragma unroll
                for (int i = 0; i < 4; i++) {
                    unsigned long long aa = pack2(a[i][j], a[i][j]);
                    ffma2(acc2[i][0], aa, bp.x);
                    ffma2(acc2[i][1], aa, bp.y);
                }
            }
        }
    }

    #pragma unroll
    for (int i = 0; i < 4; i++) {
        float2 f01 = unpack2(acc2[i][0]);
        float2 f23 = unpack2(acc2[i][1]);
        float4 v = make_float4(f01.x, f01.y, f23.x, f23.y);
        *(float4*)(C + (size_t)(row0 + (ty << 2) + i) * NE + (tx << 2)) = v;
    }
}

// ---------------------------------------------------------------------------
// Kernel B: scores + exp + row-reciprocal (MUFU-bound core unchanged from R5).
// NEW: emits p as packed bf16 t-pairs (hi/lo) via an smem exchange — the
// exact B-fragment layout mma.sync wants (low bf16 = even t).
// p[b,t,q] = exp(sum_e vc[e]*tanh(k[t,e]+q[q,e]))  (no max pass; |sjt| <= ~9)
// ---------------------------------------------------------------------------
__global__ __launch_bounds__(256) void score_kernel(const float* __restrict__ vc)
{
    __shared__ float ks[8][128];
    __shared__ float qs[2][32][129];
    __shared__ float vcs[128];
    __shared__ float pex[8][32];       // per-chunk p exchange for t-pairing

    const int b   = blockIdx.y;
    const int t0  = blockIdx.x << 3;
    const int tid = threadIdx.x;
    const int w    = tid >> 5;
    const int lane = tid & 31;

    {   // k tile [8 x 128]
        int lin = tid << 2;
        int r = lin >> 7, c = lin & 127;
        *(float4*)&ks[r][c] =
            *(const float4*)(g_kproj + (size_t)(b * NTK + t0 + r) * NE + c);
    }
    if (tid < 128) vcs[tid] = vc[tid];

    const int c0    = tid & 127;
    const int rbase = tid >> 7;
    const float* qbase = g_qproj + (size_t)b * NTQ * NE + rbase * NE + c0;

    float pref[16];
    #pragma unroll
    for (int i = 0; i < 16; i++)
        pref[i] = qbase[(size_t)(2 * i) * NE];
    #pragma unroll
    for (int i = 0; i < 16; i++)
        qs[0][rbase + 2 * i][c0] = pref[i];
    __syncthreads();

    const int t = t0 + w;
    float zsum = 0.f;
    // pair-row base for this block: t2 = t0/2 + w' (w' = 0..3)
    uint32_t* __restrict__ phrow = g_ph + ((size_t)b * NT2 + (t0 >> 1) + w) * NTQ;
    uint32_t* __restrict__ plrow = g_pl + ((size_t)b * NT2 + (t0 >> 1) + w) * NTQ;

    for (int ch = 0; ch < 16; ch++) {
        const int buf = ch & 1;
        if (ch < 15) {
            const float* src = qbase + (size_t)(ch + 1) * 32 * NE;
            #pragma unroll
            for (int i = 0; i < 16; i++)
                pref[i] = src[(size_t)(2 * i) * NE];
        }

        const float* __restrict__ kr = ks[w];
        const float* __restrict__ q0 = qs[buf][lane];
        float acc0 = 0.f;
        #pragma unroll 16
        for (int e = 0; e < 128; e++)
            acc0 += vcs[e] * tanh_fast(kr[e] + q0[e]);

        float p0 = __expf(acc0);
        pex[w][lane] = p0;
        zsum += p0;

        __syncthreads();               // pex visible; qs[buf] reads done
        if (w < 4) {                   // warps 0-3 emit packed t-pairs
            float pe = pex[2 * w][lane];
            float po = pex[2 * w + 1][lane];
            uint16_t he, le, ho, lo;
            bf16_split(pe, he, le);
            bf16_split(po, ho, lo);
            phrow[ch * 32 + lane] = ((uint32_t)ho << 16) | he;
            plrow[ch * 32 + lane] = ((uint32_t)lo << 16) | le;
        }
        if (ch < 15) {
            #pragma unroll
            for (int i = 0; i < 16; i++)
                qs[buf ^ 1][rbase + 2 * i][c0] = pref[i];
        }
        __syncthreads();               // qs refilled; pex consumed before rewrite
    }

    #pragma unroll
    for (int off = 16; off; off >>= 1)
        zsum += __shfl_xor_sync(0xffffffffu, zsum, off);
    if (lane == 0) g_zr[b * NTK + t] = 1.0f / zsum;
}

// ---------------------------------------------------------------------------
// Kernel B2: value*zr -> packed bf16 t-pairs (hi/lo). 262144 pairs.
// ---------------------------------------------------------------------------
__global__ __launch_bounds__(256) void conv_kernel(const float* __restrict__ value)
{
    int idx = blockIdx.x * 256 + threadIdx.x;      // [b][d][t2]
    int b  = idx >> 16;
    int d  = (idx >> 8) & 255;
    int t2 = idx & 255;

    float2 v2 = *(const float2*)(value + ((size_t)(b * NF + d) << 9) + 2 * t2);
    float e = v2.x * g_zr[b * NTK + 2 * t2];
    float o = v2.y * g_zr[b * NTK + 2 * t2 + 1];

    uint16_t he, le, ho, lo;
    bf16_split(e, he, le);
    bf16_split(o, ho, lo);
    g_vh[idx] = ((uint32_t)ho << 16) | he;
    g_vl[idx] = ((uint32_t)lo << 16) | le;
}

// ---------------------------------------------------------------------------
// Kernel C: out[b,d,q] = sum_t vzr[d,t] * p[t,q]   via mma.sync bf16 3-term
// split (AhBh + AhBl + AlBh), fp32 accumulators.
// Block tile 64(m=d) x 64(n=q), K=512(t) in 16 stages of 32t (16 t2-rows).
// 256 threads = 8 warps (2m x 4n), warp tile 32x16 -> 2x2 frags.
// grid = 8 x 4 x 4 = 128 blocks = single wave.
// smem strides: A 20 words/row, B 72 words/row — both conflict-free for the
// fragment gathers ((20g+t)%32 and (8t+g)%32 bijective over the warp).
// ---------------------------------------------------------------------------
__global__ __launch_bounds__(256) void out_kernel(float* __restrict__ out)
{
    __shared__ uint32_t Ah[2][64][20];   // data cols 0..15 (16 t2)
    __shared__ uint32_t Al[2][64][20];
    __shared__ uint32_t Bh[2][16][72];   // data cols 0..63 (64 q)
    __shared__ uint32_t Bl[2][16][72];

    const int b  = blockIdx.z;
    const int n0 = blockIdx.x << 6;
    const int m0 = blockIdx.y << 6;
    const int tid = threadIdx.x;
    const int w    = tid >> 5;
    const int lane = tid & 31;
    const int wm   = w >> 2;             // 0-1
    const int wn   = w & 3;              // 0-3
    const int grp  = lane >> 2;          // 0-7
    const int tig  = lane & 3;           // 0-3

    const uint32_t* vhp = g_vh + (size_t)(b * NF + m0) * NT2;
    const uint32_t* vlp = g_vl + (size_t)(b * NF + m0) * NT2;
    const uint32_t* php = g_ph + (size_t)b * NT2 * NTQ + n0;
    const uint32_t* plp = g_pl + (size_t)b * NT2 * NTQ + n0;

    const int am = tid >> 2, ac = (tid & 3) << 2;    // A: 64 rows x 4 chunks
    const int br = tid >> 4, bc = (tid & 15) << 2;   // B: 16 rows x 16 chunks

    auto issue_stage = [&](int st) {
        const int bufi = st & 1;
        const int kk2  = st << 4;        // t2 offset
        cp16(smem_u32(&Ah[bufi][am][ac]), vhp + (size_t)am * NT2 + kk2 + ac);
        cp16(smem_u32(&Al[bufi][am][ac]), vlp + (size_t)am * NT2 + kk2 + ac);
        cp16(smem_u32(&Bh[bufi][br][bc]), php + (size_t)(kk2 + br) * NTQ + bc);
        cp16(smem_u32(&Bl[bufi][br][bc]), plp + (size_t)(kk2 + br) * NTQ + bc);
        cp_commit();
    };

    issue_stage(0);

    float acc[2][2][4];
    #pragma unroll
    for (int i = 0; i < 2; i++)
        #pragma unroll
        for (int j = 0; j < 2; j++)
            #pragma unroll
            for (int r = 0; r < 4; r++) acc[i][j][r] = 0.f;

    #pragma unroll
    for (int it = 0; it < 16; it++) {
        const int bufi = it & 1;
        cp_wait<0>();
        __syncthreads();
        if (it < 15) issue_stage(it + 1);

        #pragma unroll
        for (int s = 0; s < 2; s++) {            // two k16 steps per stage
            uint32_t ah[2][4], al[2][4];
            #pragma unroll
            for (int mf = 0; mf < 2; mf++) {
                const int mb = wm * 32 + mf * 16;
                const int kc = s * 8 + tig;
                ah[mf][0] = Ah[bufi][mb + grp    ][kc];
                ah[mf][1] = Ah[bufi][mb + grp + 8][kc];
                ah[mf][2] = Ah[bufi][mb + grp    ][kc + 4];
                ah[mf][3] = Ah[bufi][mb + grp + 8][kc + 4];
                al[mf][0] = Al[bufi][mb + grp    ][kc];
                al[mf][1] = Al[bufi][mb + grp + 8][kc];
                al[mf][2] = Al[bufi][mb + grp    ][kc + 4];
                al[mf][3] = Al[bufi][mb + grp + 8][kc + 4];
            }
            #pragma unroll
            for (int nf = 0; nf < 2; nf++) {
                const int nb = wn * 16 + nf * 8 + grp;
                const int kr = s * 8 + tig;
                uint32_t bh0 = Bh[bufi][kr    ][nb];
                uint32_t bh1 = Bh[bufi][kr + 4][nb];
                uint32_t bl0 = Bl[bufi][kr    ][nb];
                uint32_t bl1 = Bl[bufi][kr + 4][nb];
                #pragma unroll
                for (int mf = 0; mf < 2; mf++) {
                    mma_bf16(acc[mf][nf], ah[mf], bh0, bh1);
                    mma_bf16(acc[mf][nf], ah[mf], bl0, bl1);
                    mma_bf16(acc[mf][nf], al[mf], bh0, bh1);
                }
            }
        }
    }

    // epilogue
    #pragma unroll
    for (int mf = 0; mf < 2; mf++) {
        #pragma unroll
        for (int nf = 0; nf < 2; nf++) {
            const int row = m0 + wm * 32 + mf * 16 + grp;
            const int col = n0 + wn * 16 + nf * 8 + tig * 2;
            float* dst0 = out + (size_t)(b * NF + row) * NTQ + col;
            float* dst1 = dst0 + 8 * NTQ;
            *(float2*)dst0 = make_float2(acc[mf][nf][0], acc[mf][nf][1]);
            *(float2*)dst1 = make_float2(acc[mf][nf][2], acc[mf][nf][3]);
        }
    }
}

// ---------------------------------------------------------------------------
extern "C" void kernel_launch(void* const* d_in, const int* in_sizes, int n_in,
                              void* d_out, int out_size)
{
    const float* query = (const float*)d_in[0];
    const float* key   = (const float*)d_in[1];
    const float* value = (const float*)d_in[2];
    const float* W1    = (const float*)d_in[3];
    const float* W2    = (const float*)d_in[4];
    const float* vc    = (const float*)d_in[5];
    float* out = (float*)d_out;

    proj_kernel <<<dim3(64, 2), 256>>>(query, key, W1, W2);
    score_kernel<<<dim3(64, 4), 256>>>(vc);
    conv_kernel <<<1024, 256>>>(value);
    out_kernel  <<<dim3(8, 4, 4), 256>>>(out);
}